// round 8
// baseline (speedup 1.0000x reference)
#include <cuda_runtime.h>
#include <math.h>

// Born-Wolf PSF: params (16,64,2) -> psf (16,64,25,25,25), normalized.
// Fused single kernel, one (b,c) pair per block.
//   phase1: A[i][r] = J0(kn*(r/2)*rho_i)*rho_i*tw_i  (f32x2 J0, conflict-free STS)
//   phase3: plane[z][r] = |sum_i A*e^{-iw}|^2; z-PAIR register tiling, rotor kept
//           in broadcast-packed f32x2 state (no per-iter register-dup MOVs)
//   phase4: colsum dot constexpr W[] -> norm
//   phase6: radial bilinear interp from constexpr pixel table + z-mirror + write

#define NHALF 13
#define NR    35
#define NRP   36
#define NI    101

typedef unsigned long long ull;

// ---------------- compile-time geometry tables ----------------
constexpr double csqrt_(double x) {
    double g = x > 1.0 ? x : 1.0;
    for (int i = 0; i < 64; ++i) g = 0.5 * (g + x / g);
    return g;
}
struct alignas(16) PixEntry { float d1, d2; int i1, pad; };
struct Tabs {
    PixEntry pix[625];
    float W[40];
    constexpr Tabs() : pix(), W() {
        double Wd[40] = {};
        for (int yy = 0; yy < 25; ++yy)
            for (int xx = 0; xx < 25; ++xx) {
                double dx = xx - 12, dy = yy - 12;
                double rp = csqrt_(dx * dx + dy * dy);
                double t2 = 2.0 * rp;
                int i1 = (int)t2;
                double d1 = t2 - (double)i1;
                int q = yy * 25 + xx;
                pix[q].d1 = (float)d1;
                pix[q].d2 = (float)(1.0 - d1);
                pix[q].i1 = i1;
                pix[q].pad = 0;
                Wd[i1]     += 1.0 - d1;
                Wd[i1 + 1] += d1;
            }
        for (int i = 0; i < 40; ++i) W[i] = (float)Wd[i];
    }
};
__device__ constexpr Tabs g_tabs{};

// ---------------- f32x2 packed helpers (sm_100+) ----------------
__device__ __forceinline__ ull pack2(float lo, float hi) {
    ull r; asm("mov.b64 %0, {%1,%2};" : "=l"(r) : "f"(lo), "f"(hi)); return r;
}
__device__ __forceinline__ void unpack2(ull v, float& lo, float& hi) {
    asm("mov.b64 {%0,%1}, %2;" : "=f"(lo), "=f"(hi) : "l"(v));
}
__device__ __forceinline__ ull ffma2(ull a, ull b, ull c) {
    ull d; asm("fma.rn.f32x2 %0, %1, %2, %3;" : "=l"(d) : "l"(a), "l"(b), "l"(c)); return d;
}
__device__ __forceinline__ ull fmul2(ull a, ull b) {
    ull d; asm("mul.rn.f32x2 %0, %1, %2;" : "=l"(d) : "l"(a), "l"(b)); return d;
}
__device__ __forceinline__ ull fadd2(ull a, ull b) {
    ull d; asm("add.rn.f32x2 %0, %1, %2;" : "=l"(d) : "l"(a), "l"(b)); return d;
}
#define C2(c) pack2((c), (c))

// Accurate sincos for |x| up to ~1000: Cody-Waite 2-pi reduction + __sincosf.
__device__ __forceinline__ void rsincos(float x, float* s, float* c) {
    float q = rintf(x * 0.15915494309189535f);
    float r = fmaf(q, -6.28125f, x);
    r = fmaf(q, -1.9353071795864769e-3f, r);
    __sincosf(r, s, c);
}

// Scalar J0 (A&S rational approx, matches reference), fast divides.
__device__ __forceinline__ float bessel_j0f(float x) {
    float ax = fabsf(x);
    if (ax <= 8.0f) {
        float y = x * x;
        float num = -184.9052456f;
        num = fmaf(num, y, 77392.33017f);
        num = fmaf(num, y, -11214424.18f);
        num = fmaf(num, y, 651619640.7f);
        num = fmaf(num, y, -13362590354.0f);
        num = fmaf(num, y, 57568490574.0f);
        float den = y + 267.8532712f;
        den = fmaf(den, y, 59272.64853f);
        den = fmaf(den, y, 9494680.718f);
        den = fmaf(den, y, 1029532985.0f);
        den = fmaf(den, y, 57568490411.0f);
        return __fdividef(num, den);
    } else {
        float z = __fdividef(8.0f, ax);
        float y2 = z * z;
        float p1 = 0.2093887211e-6f;
        p1 = fmaf(p1, y2, -0.2073370639e-5f);
        p1 = fmaf(p1, y2, 0.2734510407e-4f);
        p1 = fmaf(p1, y2, -0.1098628627e-2f);
        p1 = fmaf(p1, y2, 1.0f);
        float p2 = -0.934935152e-7f;
        p2 = fmaf(p2, y2, 0.7621095161e-6f);
        p2 = fmaf(p2, y2, -0.6911147651e-5f);
        p2 = fmaf(p2, y2, 0.1430488765e-3f);
        p2 = fmaf(p2, y2, -0.1562499995e-1f);
        float s, c;
        rsincos(ax - 0.785398164f, &s, &c);
        return rsqrtf(ax) * 0.7978845608028654f * (c * p1 - z * s * p2);
    }
}

// Packed J0 for a pair of non-negative args (x0 <= x1).
__device__ __forceinline__ void j0_pair(float x0, float x1, float& r0, float& r1) {
    if (x1 <= 8.0f) {
        ull x = pack2(x0, x1);
        ull y = fmul2(x, x);
        ull num = C2(-184.9052456f);
        num = ffma2(num, y, C2(77392.33017f));
        num = ffma2(num, y, C2(-11214424.18f));
        num = ffma2(num, y, C2(651619640.7f));
        num = ffma2(num, y, C2(-13362590354.0f));
        num = ffma2(num, y, C2(57568490574.0f));
        ull den = fadd2(y, C2(267.8532712f));
        den = ffma2(den, y, C2(59272.64853f));
        den = ffma2(den, y, C2(9494680.718f));
        den = ffma2(den, y, C2(1029532985.0f));
        den = ffma2(den, y, C2(57568490411.0f));
        float n0, n1, d0, d1;
        unpack2(num, n0, n1); unpack2(den, d0, d1);
        r0 = __fdividef(n0, d0);
        r1 = __fdividef(n1, d1);
    } else if (x0 > 8.0f) {
        float z0 = __fdividef(8.0f, x0), z1 = __fdividef(8.0f, x1);
        ull z = pack2(z0, z1);
        ull y2 = fmul2(z, z);
        ull p1 = C2(0.2093887211e-6f);
        p1 = ffma2(p1, y2, C2(-0.2073370639e-5f));
        p1 = ffma2(p1, y2, C2(0.2734510407e-4f));
        p1 = ffma2(p1, y2, C2(-0.1098628627e-2f));
        p1 = ffma2(p1, y2, C2(1.0f));
        ull p2 = C2(-0.934935152e-7f);
        p2 = ffma2(p2, y2, C2(0.7621095161e-6f));
        p2 = ffma2(p2, y2, C2(-0.6911147651e-5f));
        p2 = ffma2(p2, y2, C2(0.1430488765e-3f));
        p2 = ffma2(p2, y2, C2(-0.1562499995e-1f));
        float p1a, p1b, p2a, p2b;
        unpack2(p1, p1a, p1b); unpack2(p2, p2a, p2b);
        float s0, c0, s1, c1;
        rsincos(x0 - 0.785398164f, &s0, &c0);
        rsincos(x1 - 0.785398164f, &s1, &c1);
        r0 = rsqrtf(x0) * 0.7978845608028654f * (c0 * p1a - z0 * s0 * p2a);
        r1 = rsqrtf(x1) * 0.7978845608028654f * (c1 * p1b - z1 * s1 * p2b);
    } else {
        r0 = bessel_j0f(x0);
        r1 = bessel_j0f(x1);
    }
}

// Packed double-rotor state for w(i) = base*i^2 (both f32x2 lanes identical).
struct Rotor {
    ull CC, SS, CD, SD, NSD;   // cos, sin, step-cos, step-sin, -step-sin
    ull CP, SP;                // step-of-step (invariant)
};

__device__ __forceinline__ Rotor rot_init(float base, int ib) {
    float c, s, cd, sd, cp, sp;
    float fib = (float)ib;
    rsincos(base * fib * fib, &s, &c);                 // e^{j w(ib)}
    rsincos(base * (2.0f * fib + 1.0f), &sd, &cd);     // step at ib
    rsincos(2.0f * base, &sp, &cp);                    // step-of-step
    Rotor R;
    R.CC = C2(c); R.SS = C2(s);
    R.CD = C2(cd); R.SD = C2(sd); R.NSD = C2(-sd);
    R.CP = C2(cp); R.SP = C2(sp);
    return R;
}

// one accumulate + rotor advance (13 f32x2 ops, no scalar MOV duplication)
__device__ __forceinline__ void rot_step(Rotor& R, ull a01, ull a23,
                                         ull& re01, ull& re23, ull& im01, ull& im23,
                                         ull NEG1) {
    re01 = ffma2(a01, R.CC, re01);
    re23 = ffma2(a23, R.CC, re23);
    im01 = ffma2(a01, R.SS, im01);
    im23 = ffma2(a23, R.SS, im23);
    ull ncc = ffma2(R.SS, R.NSD, fmul2(R.CC, R.CD));   // c*cd - s*sd
    ull nss = ffma2(R.CC, R.SD,  fmul2(R.SS, R.CD));   // s*cd + c*sd
    ull ncd = ffma2(R.NSD, R.SP, fmul2(R.CD, R.CP));   // cd*cp - sd*sp
    ull nsd = ffma2(R.CD,  R.SP, fmul2(R.SD, R.CP));   // sd*cp + cd*sp
    R.CC = ncc; R.SS = nss; R.CD = ncd; R.SD = nsd;
    R.NSD = fmul2(nsd, NEG1);
}

__global__ __launch_bounds__(256, 4)
void bw_psf_kernel(const float* __restrict__ params, float* __restrict__ out) {
    const int p = blockIdx.x;
    const int tid = threadIdx.x;
    const int lane = tid & 31;

    __shared__ __align__(16) float sA[NI][NRP];   // 14.5 KB
    __shared__ float  sPlane[NHALF + 1][NRP];     // 2.0 KB
    __shared__ float2 sPair[NHALF][40];           // 4.2 KB
    __shared__ float  sPartF[3][63][17];          // 12.9 KB
    __shared__ float  sWcol[40];

    const float lam = fabsf(params[2 * p]);
    const float n   = fabsf(params[2 * p + 1]);
    const float k   = 6.2831853071795864769f / lam;
    const float kn  = k * n;
    const float kz2 = 0.5f * k * n * n;

    // ---- Phase 1: A[i][r], r-fastest mapping (conflict-free STS) ----
    for (int job = tid; job < 51 * NR; job += 256) {
        int ii = job / NR;
        int r  = job - ii * NR;
        int i0 = 2 * ii;
        int i1 = (i0 < NI - 1) ? i0 + 1 : NI - 1;
        float a = kn * (0.5f * (float)r);
        float rho0 = (float)i0 * 0.01f, rho1 = (float)i1 * 0.01f;
        float j0a, j0b;
        j0_pair(a * rho0, a * rho1, j0a, j0b);
        float tw0 = (i0 == 0 || i0 == NI - 1) ? 0.005f : 0.01f;
        float tw1 = (i1 == NI - 1) ? 0.005f : 0.01f;
        sA[i0][r] = j0a * rho0 * tw0;
        if (i1 != i0) sA[i1][r] = j0b * rho1 * tw1;
    }
    __syncthreads();

    // ---- Phase 3: z-pair tiled matmul, 252 threads (7 zp x 9 rq x 4 i-groups) ----
    const int g   = tid >> 6;        // i-group 0..3
    const int t64 = tid & 63;
    const bool act = (t64 < 63);
    int zp = 0, r0 = 0;
    float vacc[16];
    #pragma unroll
    for (int j = 0; j < 16; ++j) vacc[j] = 0.0f;
    if (act) {
        zp = t64 / 9;
        r0 = (t64 - zp * 9) * 4;
        const float dz = kz2 * 1e-4f;
        const float b0 = dz * (float)(2 * zp);
        const float b1 = b0 + dz;
        const int ib = (g == 0) ? 0 : (g * 25 + 1);   // 0, 26, 51, 76
        const int ie = (g + 1) * 25 + 1;              // 26, 51, 76, 101
        const ull NEG1 = C2(-1.0f);
        Rotor R0 = rot_init(b0, ib);
        Rotor R1 = rot_init(b1, ib);
        ull re01a = 0, re23a = 0, im01a = 0, im23a = 0;
        ull re01b = 0, re23b = 0, im01b = 0, im23b = 0;
        #pragma unroll 2
        for (int i = ib; i < ie; ++i) {
            float4 av = *(const float4*)&sA[i][r0];
            ull a01 = pack2(av.x, av.y), a23 = pack2(av.z, av.w);
            rot_step(R0, a01, a23, re01a, re23a, im01a, im23a, NEG1);
            rot_step(R1, a01, a23, re01b, re23b, im01b, im23b, NEG1);
        }
        unpack2(re01a, vacc[0], vacc[1]);   unpack2(re23a, vacc[2],  vacc[3]);
        unpack2(im01a, vacc[4], vacc[5]);   unpack2(im23a, vacc[6],  vacc[7]);
        unpack2(re01b, vacc[8], vacc[9]);   unpack2(re23b, vacc[10], vacc[11]);
        unpack2(im01b, vacc[12], vacc[13]); unpack2(im23b, vacc[14], vacc[15]);
        if (g > 0) {
            float* d = sPartF[g - 1][t64];
            #pragma unroll
            for (int j = 0; j < 16; ++j) d[j] = vacc[j];
        }
    }
    __syncthreads();
    if (act && g == 0) {
        #pragma unroll
        for (int gg = 0; gg < 3; ++gg) {
            const float* d = sPartF[gg][t64];
            #pragma unroll
            for (int j = 0; j < 16; ++j) vacc[j] += d[j];
        }
        const int z0 = 2 * zp, z1 = z0 + 1;
        sPlane[z0][r0]     = vacc[0] * vacc[0] + vacc[4] * vacc[4];
        sPlane[z0][r0 + 1] = vacc[1] * vacc[1] + vacc[5] * vacc[5];
        sPlane[z0][r0 + 2] = vacc[2] * vacc[2] + vacc[6] * vacc[6];
        sPlane[z1][r0]     = vacc[8] * vacc[8] + vacc[12] * vacc[12];
        sPlane[z1][r0 + 1] = vacc[9] * vacc[9] + vacc[13] * vacc[13];
        sPlane[z1][r0 + 2] = vacc[10] * vacc[10] + vacc[14] * vacc[14];
        if (r0 + 3 < NR) {
            sPlane[z0][r0 + 3] = vacc[3] * vacc[3] + vacc[7] * vacc[7];
            sPlane[z1][r0 + 3] = vacc[11] * vacc[11] + vacc[15] * vacc[15];
        }
    }
    __syncthreads();

    // ---- Phase 4: colsum dot W (norm prep) + pair table ----
    if (tid < NR) {
        float s = sPlane[0][tid];
        #pragma unroll
        for (int zz = 1; zz < NHALF; ++zz) s += 2.0f * sPlane[zz][tid];
        sWcol[tid] = s * g_tabs.W[tid];
    }
    for (int idx = tid; idx < NHALF * NR; idx += 256) {
        int zz = idx / NR, r = idx - zz * NR;
        float lo = sPlane[zz][r];
        float hi = (r < NR - 1) ? sPlane[zz][r + 1] : 0.0f;
        sPair[zz][r] = make_float2(lo, hi);
    }
    __syncthreads();

    // ---- redundant per-warp reduction of sWcol -> inv (no extra barrier) ----
    float v = (lane < NR) ? sWcol[lane] : 0.0f;
    if (lane < 3) v += sWcol[32 + lane];
    #pragma unroll
    for (int o = 16; o; o >>= 1) v += __shfl_xor_sync(0xFFFFFFFFu, v, o);
    const float inv = __fdividef(1.0f, v);

    // ---- Phase 6: interp from constexpr pixel table + z-mirror + write ----
    const float4* ptab = reinterpret_cast<const float4*>(g_tabs.pix);
    for (int pix = tid; pix < 625; pix += 256) {
        float4 e = ptab[pix];                 // {d1, d2, i1 bits, pad}
        int i1 = __float_as_int(e.z);
        float d1 = e.x * inv, d2 = e.y * inv;
        float vv[NHALF];
        #pragma unroll
        for (int zo = 0; zo < NHALF; ++zo) {
            float2 pr = sPair[zo][i1];        // LDS.64
            vv[zo] = fmaf(d1, pr.y, d2 * pr.x);
        }
        float* po = out + (size_t)p * 15625 + pix;
        #pragma unroll
        for (int zz = 0; zz < 25; ++zz) {
            int zo = (zz < 12) ? (12 - zz) : (zz - 12);
            po[zz * 625] = vv[zo];
        }
    }
}

extern "C" void kernel_launch(void* const* d_in, const int* in_sizes, int n_in,
                              void* d_out, int out_size) {
    const float* params = (const float*)d_in[0];
    float* out = (float*)d_out;
    int npairs = in_sizes[0] / 2;   // 16*64 = 1024
    bw_psf_kernel<<<npairs, 256>>>(params, out);
}

// round 9
// speedup vs baseline: 1.1345x; 1.1345x over previous
#include <cuda_runtime.h>
#include <math.h>

// Born-Wolf PSF: params (16,64,2) -> psf (16,64,25,25,25), normalized.
// Fused single kernel, one (b,c) pair per block. R7 structure at 6 blocks/SM.
//   phase1: A[i][r] = J0(kn*(r/2)*rho_i)*rho_i*tw_i  (f32x2 J0, conflict-free STS)
//   phase3: plane[z][r] = |sum_i A*e^{-iw}|^2; z-PAIR register tiling, scalar
//           double-rotor, rho split 4 ways (7 zp x 9 rq x 4 i-groups)
//   phase4: colsum dot constexpr W[] -> norm
//   phase6: radial bilinear interp from constexpr pixel table + z-mirror + write

#define NHALF 13
#define NR    35
#define NRP   36
#define NI    101

typedef unsigned long long ull;

// ---------------- compile-time geometry tables ----------------
constexpr double csqrt_(double x) {
    double g = x > 1.0 ? x : 1.0;
    for (int i = 0; i < 64; ++i) g = 0.5 * (g + x / g);
    return g;
}
struct alignas(16) PixEntry { float d1, d2; int i1, pad; };
struct Tabs {
    PixEntry pix[625];
    float W[40];
    constexpr Tabs() : pix(), W() {
        double Wd[40] = {};
        for (int yy = 0; yy < 25; ++yy)
            for (int xx = 0; xx < 25; ++xx) {
                double dx = xx - 12, dy = yy - 12;
                double rp = csqrt_(dx * dx + dy * dy);
                double t2 = 2.0 * rp;
                int i1 = (int)t2;
                double d1 = t2 - (double)i1;
                int q = yy * 25 + xx;
                pix[q].d1 = (float)d1;
                pix[q].d2 = (float)(1.0 - d1);
                pix[q].i1 = i1;
                pix[q].pad = 0;
                Wd[i1]     += 1.0 - d1;
                Wd[i1 + 1] += d1;
            }
        for (int i = 0; i < 40; ++i) W[i] = (float)Wd[i];
    }
};
__device__ constexpr Tabs g_tabs{};

// ---------------- f32x2 packed helpers (sm_100+) ----------------
__device__ __forceinline__ ull pack2(float lo, float hi) {
    ull r; asm("mov.b64 %0, {%1,%2};" : "=l"(r) : "f"(lo), "f"(hi)); return r;
}
__device__ __forceinline__ void unpack2(ull v, float& lo, float& hi) {
    asm("mov.b64 {%0,%1}, %2;" : "=f"(lo), "=f"(hi) : "l"(v));
}
__device__ __forceinline__ ull ffma2(ull a, ull b, ull c) {
    ull d; asm("fma.rn.f32x2 %0, %1, %2, %3;" : "=l"(d) : "l"(a), "l"(b), "l"(c)); return d;
}
__device__ __forceinline__ ull fmul2(ull a, ull b) {
    ull d; asm("mul.rn.f32x2 %0, %1, %2;" : "=l"(d) : "l"(a), "l"(b)); return d;
}
__device__ __forceinline__ ull fadd2(ull a, ull b) {
    ull d; asm("add.rn.f32x2 %0, %1, %2;" : "=l"(d) : "l"(a), "l"(b)); return d;
}
#define C2(c) pack2((c), (c))

// Accurate sincos for |x| up to ~1000: Cody-Waite 2-pi reduction + __sincosf.
__device__ __forceinline__ void rsincos(float x, float* s, float* c) {
    float q = rintf(x * 0.15915494309189535f);
    float r = fmaf(q, -6.28125f, x);
    r = fmaf(q, -1.9353071795864769e-3f, r);
    __sincosf(r, s, c);
}

// Scalar J0 (A&S rational approx, matches reference), fast divides.
__device__ __forceinline__ float bessel_j0f(float x) {
    float ax = fabsf(x);
    if (ax <= 8.0f) {
        float y = x * x;
        float num = -184.9052456f;
        num = fmaf(num, y, 77392.33017f);
        num = fmaf(num, y, -11214424.18f);
        num = fmaf(num, y, 651619640.7f);
        num = fmaf(num, y, -13362590354.0f);
        num = fmaf(num, y, 57568490574.0f);
        float den = y + 267.8532712f;
        den = fmaf(den, y, 59272.64853f);
        den = fmaf(den, y, 9494680.718f);
        den = fmaf(den, y, 1029532985.0f);
        den = fmaf(den, y, 57568490411.0f);
        return __fdividef(num, den);
    } else {
        float z = __fdividef(8.0f, ax);
        float y2 = z * z;
        float p1 = 0.2093887211e-6f;
        p1 = fmaf(p1, y2, -0.2073370639e-5f);
        p1 = fmaf(p1, y2, 0.2734510407e-4f);
        p1 = fmaf(p1, y2, -0.1098628627e-2f);
        p1 = fmaf(p1, y2, 1.0f);
        float p2 = -0.934935152e-7f;
        p2 = fmaf(p2, y2, 0.7621095161e-6f);
        p2 = fmaf(p2, y2, -0.6911147651e-5f);
        p2 = fmaf(p2, y2, 0.1430488765e-3f);
        p2 = fmaf(p2, y2, -0.1562499995e-1f);
        float s, c;
        rsincos(ax - 0.785398164f, &s, &c);
        return rsqrtf(ax) * 0.7978845608028654f * (c * p1 - z * s * p2);
    }
}

// Packed J0 for a pair of non-negative args (x0 <= x1).
__device__ __forceinline__ void j0_pair(float x0, float x1, float& r0, float& r1) {
    if (x1 <= 8.0f) {
        ull x = pack2(x0, x1);
        ull y = fmul2(x, x);
        ull num = C2(-184.9052456f);
        num = ffma2(num, y, C2(77392.33017f));
        num = ffma2(num, y, C2(-11214424.18f));
        num = ffma2(num, y, C2(651619640.7f));
        num = ffma2(num, y, C2(-13362590354.0f));
        num = ffma2(num, y, C2(57568490574.0f));
        ull den = fadd2(y, C2(267.8532712f));
        den = ffma2(den, y, C2(59272.64853f));
        den = ffma2(den, y, C2(9494680.718f));
        den = ffma2(den, y, C2(1029532985.0f));
        den = ffma2(den, y, C2(57568490411.0f));
        float n0, n1, d0, d1;
        unpack2(num, n0, n1); unpack2(den, d0, d1);
        r0 = __fdividef(n0, d0);
        r1 = __fdividef(n1, d1);
    } else if (x0 > 8.0f) {
        float z0 = __fdividef(8.0f, x0), z1 = __fdividef(8.0f, x1);
        ull z = pack2(z0, z1);
        ull y2 = fmul2(z, z);
        ull p1 = C2(0.2093887211e-6f);
        p1 = ffma2(p1, y2, C2(-0.2073370639e-5f));
        p1 = ffma2(p1, y2, C2(0.2734510407e-4f));
        p1 = ffma2(p1, y2, C2(-0.1098628627e-2f));
        p1 = ffma2(p1, y2, C2(1.0f));
        ull p2 = C2(-0.934935152e-7f);
        p2 = ffma2(p2, y2, C2(0.7621095161e-6f));
        p2 = ffma2(p2, y2, C2(-0.6911147651e-5f));
        p2 = ffma2(p2, y2, C2(0.1430488765e-3f));
        p2 = ffma2(p2, y2, C2(-0.1562499995e-1f));
        float p1a, p1b, p2a, p2b;
        unpack2(p1, p1a, p1b); unpack2(p2, p2a, p2b);
        float s0, c0, s1, c1;
        rsincos(x0 - 0.785398164f, &s0, &c0);
        rsincos(x1 - 0.785398164f, &s1, &c1);
        r0 = rsqrtf(x0) * 0.7978845608028654f * (c0 * p1a - z0 * s0 * p2a);
        r1 = rsqrtf(x1) * 0.7978845608028654f * (c1 * p1b - z1 * s1 * p2b);
    } else {
        r0 = bessel_j0f(x0);
        r1 = bessel_j0f(x1);
    }
}

// double-rotor init for w(i) = base*i^2 starting at i = ib
__device__ __forceinline__ void rot_init(float base, int ib,
                                         float& c, float& s, float& cd, float& sd,
                                         float& cp, float& sp) {
    float fib = (float)ib;
    rsincos(base * fib * fib, &s, &c);                 // e^{j w(ib)}
    rsincos(base * (2.0f * fib + 1.0f), &sd, &cd);     // step at ib
    rsincos(2.0f * base, &sp, &cp);                    // step-of-step
}

__global__ __launch_bounds__(256, 6)
void bw_psf_kernel(const float* __restrict__ params, float* __restrict__ out) {
    const int p = blockIdx.x;
    const int tid = threadIdx.x;
    const int lane = tid & 31;

    __shared__ __align__(16) float sA[NI][NRP];   // 14.5 KB
    __shared__ float  sPlane[NHALF + 1][NRP];     // 2.0 KB
    __shared__ float2 sPair[NHALF][40];           // 4.2 KB
    __shared__ float  sPartF[3][63][17];          // 12.9 KB
    __shared__ float  sWcol[40];

    const float lam = fabsf(params[2 * p]);
    const float n   = fabsf(params[2 * p + 1]);
    const float k   = 6.2831853071795864769f / lam;
    const float kn  = k * n;
    const float kz2 = 0.5f * k * n * n;

    // ---- Phase 1: A[i][r], r-fastest mapping (conflict-free STS) ----
    for (int job = tid; job < 51 * NR; job += 256) {
        int ii = job / NR;
        int r  = job - ii * NR;
        int i0 = 2 * ii;
        int i1 = (i0 < NI - 1) ? i0 + 1 : NI - 1;
        float a = kn * (0.5f * (float)r);
        float rho0 = (float)i0 * 0.01f, rho1 = (float)i1 * 0.01f;
        float j0a, j0b;
        j0_pair(a * rho0, a * rho1, j0a, j0b);
        float tw0 = (i0 == 0 || i0 == NI - 1) ? 0.005f : 0.01f;
        float tw1 = (i1 == NI - 1) ? 0.005f : 0.01f;
        sA[i0][r] = j0a * rho0 * tw0;
        if (i1 != i0) sA[i1][r] = j0b * rho1 * tw1;
    }
    __syncthreads();

    // ---- Phase 3: z-pair tiled matmul, 252 threads (7 zp x 9 rq x 4 i-groups) ----
    const int g   = tid >> 6;        // i-group 0..3
    const int t64 = tid & 63;
    const bool act = (t64 < 63);
    int zp = 0, r0 = 0;
    ull re01a = 0, re23a = 0, im01a = 0, im23a = 0;
    ull re01b = 0, re23b = 0, im01b = 0, im23b = 0;
    if (act) {
        zp = t64 / 9;
        r0 = (t64 - zp * 9) * 4;
        const float dz = kz2 * 1e-4f;
        const float b0 = dz * (float)(2 * zp);
        const float b1 = b0 + dz;
        const int ib = (g == 0) ? 0 : (g * 25 + 1);   // 0, 26, 51, 76
        const int ie = (g + 1) * 25 + 1;              // 26, 51, 76, 101
        float c0, s0, cd0, sd0, cp0, sp0;
        float c1, s1, cd1, sd1, cp1, sp1;
        rot_init(b0, ib, c0, s0, cd0, sd0, cp0, sp0);
        rot_init(b1, ib, c1, s1, cd1, sd1, cp1, sp1);
        #pragma unroll 2
        for (int i = ib; i < ie; ++i) {
            float4 av = *(const float4*)&sA[i][r0];
            ull a01 = pack2(av.x, av.y), a23 = pack2(av.z, av.w);
            {
                ull cc = pack2(c0, c0), ss = pack2(s0, s0);
                re01a = ffma2(a01, cc, re01a);
                re23a = ffma2(a23, cc, re23a);
                im01a = ffma2(a01, ss, im01a);
                im23a = ffma2(a23, ss, im23a);
                float cn = fmaf(c0, cd0, -(s0 * sd0));
                float sn = fmaf(s0, cd0,  (c0 * sd0));
                c0 = cn; s0 = sn;
                float cdn = fmaf(cd0, cp0, -(sd0 * sp0));
                float sdn = fmaf(sd0, cp0,  (cd0 * sp0));
                cd0 = cdn; sd0 = sdn;
            }
            {
                ull cc = pack2(c1, c1), ss = pack2(s1, s1);
                re01b = ffma2(a01, cc, re01b);
                re23b = ffma2(a23, cc, re23b);
                im01b = ffma2(a01, ss, im01b);
                im23b = ffma2(a23, ss, im23b);
                float cn = fmaf(c1, cd1, -(s1 * sd1));
                float sn = fmaf(s1, cd1,  (c1 * sd1));
                c1 = cn; s1 = sn;
                float cdn = fmaf(cd1, cp1, -(sd1 * sp1));
                float sdn = fmaf(sd1, cp1,  (cd1 * sp1));
                cd1 = cdn; sd1 = sdn;
            }
        }
        if (g > 0) {
            float* d = sPartF[g - 1][t64];
            float v0, v1;
            unpack2(re01a, v0, v1); d[0]  = v0; d[1]  = v1;
            unpack2(re23a, v0, v1); d[2]  = v0; d[3]  = v1;
            unpack2(im01a, v0, v1); d[4]  = v0; d[5]  = v1;
            unpack2(im23a, v0, v1); d[6]  = v0; d[7]  = v1;
            unpack2(re01b, v0, v1); d[8]  = v0; d[9]  = v1;
            unpack2(re23b, v0, v1); d[10] = v0; d[11] = v1;
            unpack2(im01b, v0, v1); d[12] = v0; d[13] = v1;
            unpack2(im23b, v0, v1); d[14] = v0; d[15] = v1;
        }
    }
    __syncthreads();
    if (act && g == 0) {
        float vacc[16];
        unpack2(re01a, vacc[0], vacc[1]);   unpack2(re23a, vacc[2],  vacc[3]);
        unpack2(im01a, vacc[4], vacc[5]);   unpack2(im23a, vacc[6],  vacc[7]);
        unpack2(re01b, vacc[8], vacc[9]);   unpack2(re23b, vacc[10], vacc[11]);
        unpack2(im01b, vacc[12], vacc[13]); unpack2(im23b, vacc[14], vacc[15]);
        #pragma unroll
        for (int gg = 0; gg < 3; ++gg) {
            const float* d = sPartF[gg][t64];
            #pragma unroll
            for (int j = 0; j < 16; ++j) vacc[j] += d[j];
        }
        const int z0 = 2 * zp, z1 = z0 + 1;
        sPlane[z0][r0]     = vacc[0] * vacc[0] + vacc[4] * vacc[4];
        sPlane[z0][r0 + 1] = vacc[1] * vacc[1] + vacc[5] * vacc[5];
        sPlane[z0][r0 + 2] = vacc[2] * vacc[2] + vacc[6] * vacc[6];
        sPlane[z1][r0]     = vacc[8] * vacc[8] + vacc[12] * vacc[12];
        sPlane[z1][r0 + 1] = vacc[9] * vacc[9] + vacc[13] * vacc[13];
        sPlane[z1][r0 + 2] = vacc[10] * vacc[10] + vacc[14] * vacc[14];
        if (r0 + 3 < NR) {
            sPlane[z0][r0 + 3] = vacc[3] * vacc[3] + vacc[7] * vacc[7];
            sPlane[z1][r0 + 3] = vacc[11] * vacc[11] + vacc[15] * vacc[15];
        }
    }
    __syncthreads();

    // ---- Phase 4: colsum dot W (norm prep) + pair table ----
    if (tid < NR) {
        float s = sPlane[0][tid];
        #pragma unroll
        for (int zz = 1; zz < NHALF; ++zz) s += 2.0f * sPlane[zz][tid];
        sWcol[tid] = s * g_tabs.W[tid];
    }
    for (int idx = tid; idx < NHALF * NR; idx += 256) {
        int zz = idx / NR, r = idx - zz * NR;
        float lo = sPlane[zz][r];
        float hi = (r < NR - 1) ? sPlane[zz][r + 1] : 0.0f;
        sPair[zz][r] = make_float2(lo, hi);
    }
    __syncthreads();

    // ---- redundant per-warp reduction of sWcol -> inv (no extra barrier) ----
    float v = (lane < NR) ? sWcol[lane] : 0.0f;
    if (lane < 3) v += sWcol[32 + lane];
    #pragma unroll
    for (int o = 16; o; o >>= 1) v += __shfl_xor_sync(0xFFFFFFFFu, v, o);
    const float inv = __fdividef(1.0f, v);

    // ---- Phase 6: interp from constexpr pixel table + z-mirror + write ----
    const float4* ptab = reinterpret_cast<const float4*>(g_tabs.pix);
    for (int pix = tid; pix < 625; pix += 256) {
        float4 e = ptab[pix];                 // {d1, d2, i1 bits, pad}
        int i1 = __float_as_int(e.z);
        float d1 = e.x * inv, d2 = e.y * inv;
        float vv[NHALF];
        #pragma unroll
        for (int zo = 0; zo < NHALF; ++zo) {
            float2 pr = sPair[zo][i1];        // LDS.64
            vv[zo] = fmaf(d1, pr.y, d2 * pr.x);
        }
        float* po = out + (size_t)p * 15625 + pix;
        #pragma unroll
        for (int zz = 0; zz < 25; ++zz) {
            int zo = (zz < 12) ? (12 - zz) : (zz - 12);
            po[zz * 625] = vv[zo];
        }
    }
}

extern "C" void kernel_launch(void* const* d_in, const int* in_sizes, int n_in,
                              void* d_out, int out_size) {
    const float* params = (const float*)d_in[0];
    float* out = (float*)d_out;
    int npairs = in_sizes[0] / 2;   // 16*64 = 1024
    bw_psf_kernel<<<npairs, 256>>>(params, out);
}

// round 11
// speedup vs baseline: 1.2156x; 1.0715x over previous
#include <cuda_runtime.h>
#include <math.h>

// Born-Wolf PSF: params (16,64,2) -> psf (16,64,25,25,25), normalized.
// Fused single kernel, one (b,c) pair per block.
//   phase1: A[i][r] = J0(kn*(r/2)*rho_i)*rho_i*tw_i  (f32x2 J0, conflict-free STS)
//   phase2: packed CS table sCS4[zp][i] = (cos,sin) for z=2zp and 2zp+1
//           (101 threads on warps 4-7, one rsincos + 13-step z-rotor each)
//   phase3: plane[z][r] via z-pair tiled matmul; per iter: 2x LDS.128 + 8 ffma2
//   phase4: colsum dot constexpr W[] -> norm
//   phase6: radial bilinear interp from constexpr pixel table + z-mirror + write

#define NHALF 13
#define NR    35
#define NRP   36
#define NI    101

typedef unsigned long long ull;

// ---------------- compile-time geometry tables ----------------
constexpr double csqrt_(double x) {
    double g = x > 1.0 ? x : 1.0;
    for (int i = 0; i < 64; ++i) g = 0.5 * (g + x / g);
    return g;
}
struct alignas(16) PixEntry { float d1, d2; int i1, pad; };
struct Tabs {
    PixEntry pix[625];
    float W[40];
    constexpr Tabs() : pix(), W() {
        double Wd[40] = {};
        for (int yy = 0; yy < 25; ++yy)
            for (int xx = 0; xx < 25; ++xx) {
                double dx = xx - 12, dy = yy - 12;
                double rp = csqrt_(dx * dx + dy * dy);
                double t2 = 2.0 * rp;
                int i1 = (int)t2;
                double d1 = t2 - (double)i1;
                int q = yy * 25 + xx;
                pix[q].d1 = (float)d1;
                pix[q].d2 = (float)(1.0 - d1);
                pix[q].i1 = i1;
                pix[q].pad = 0;
                Wd[i1]     += 1.0 - d1;
                Wd[i1 + 1] += d1;
            }
        for (int i = 0; i < 40; ++i) W[i] = (float)Wd[i];
    }
};
__device__ constexpr Tabs g_tabs{};

// ---------------- f32x2 packed helpers (sm_100+) ----------------
__device__ __forceinline__ ull pack2(float lo, float hi) {
    ull r; asm("mov.b64 %0, {%1,%2};" : "=l"(r) : "f"(lo), "f"(hi)); return r;
}
__device__ __forceinline__ void unpack2(ull v, float& lo, float& hi) {
    asm("mov.b64 {%0,%1}, %2;" : "=f"(lo), "=f"(hi) : "l"(v));
}
__device__ __forceinline__ ull ffma2(ull a, ull b, ull c) {
    ull d; asm("fma.rn.f32x2 %0, %1, %2, %3;" : "=l"(d) : "l"(a), "l"(b), "l"(c)); return d;
}
__device__ __forceinline__ ull fmul2(ull a, ull b) {
    ull d; asm("mul.rn.f32x2 %0, %1, %2;" : "=l"(d) : "l"(a), "l"(b)); return d;
}
__device__ __forceinline__ ull fadd2(ull a, ull b) {
    ull d; asm("add.rn.f32x2 %0, %1, %2;" : "=l"(d) : "l"(a), "l"(b)); return d;
}
#define C2(c) pack2((c), (c))

// Accurate sincos for |x| up to ~1000: Cody-Waite 2-pi reduction + __sincosf.
__device__ __forceinline__ void rsincos(float x, float* s, float* c) {
    float q = rintf(x * 0.15915494309189535f);
    float r = fmaf(q, -6.28125f, x);
    r = fmaf(q, -1.9353071795864769e-3f, r);
    __sincosf(r, s, c);
}

// Scalar J0 (A&S rational approx, matches reference), fast divides.
__device__ __forceinline__ float bessel_j0f(float x) {
    float ax = fabsf(x);
    if (ax <= 8.0f) {
        float y = x * x;
        float num = -184.9052456f;
        num = fmaf(num, y, 77392.33017f);
        num = fmaf(num, y, -11214424.18f);
        num = fmaf(num, y, 651619640.7f);
        num = fmaf(num, y, -13362590354.0f);
        num = fmaf(num, y, 57568490574.0f);
        float den = y + 267.8532712f;
        den = fmaf(den, y, 59272.64853f);
        den = fmaf(den, y, 9494680.718f);
        den = fmaf(den, y, 1029532985.0f);
        den = fmaf(den, y, 57568490411.0f);
        return __fdividef(num, den);
    } else {
        float z = __fdividef(8.0f, ax);
        float y2 = z * z;
        float p1 = 0.2093887211e-6f;
        p1 = fmaf(p1, y2, -0.2073370639e-5f);
        p1 = fmaf(p1, y2, 0.2734510407e-4f);
        p1 = fmaf(p1, y2, -0.1098628627e-2f);
        p1 = fmaf(p1, y2, 1.0f);
        float p2 = -0.934935152e-7f;
        p2 = fmaf(p2, y2, 0.7621095161e-6f);
        p2 = fmaf(p2, y2, -0.6911147651e-5f);
        p2 = fmaf(p2, y2, 0.1430488765e-3f);
        p2 = fmaf(p2, y2, -0.1562499995e-1f);
        float s, c;
        rsincos(ax - 0.785398164f, &s, &c);
        return rsqrtf(ax) * 0.7978845608028654f * (c * p1 - z * s * p2);
    }
}

// Packed J0 for a pair of non-negative args (x0 <= x1).
__device__ __forceinline__ void j0_pair(float x0, float x1, float& r0, float& r1) {
    if (x1 <= 8.0f) {
        ull x = pack2(x0, x1);
        ull y = fmul2(x, x);
        ull num = C2(-184.9052456f);
        num = ffma2(num, y, C2(77392.33017f));
        num = ffma2(num, y, C2(-11214424.18f));
        num = ffma2(num, y, C2(651619640.7f));
        num = ffma2(num, y, C2(-13362590354.0f));
        num = ffma2(num, y, C2(57568490574.0f));
        ull den = fadd2(y, C2(267.8532712f));
        den = ffma2(den, y, C2(59272.64853f));
        den = ffma2(den, y, C2(9494680.718f));
        den = ffma2(den, y, C2(1029532985.0f));
        den = ffma2(den, y, C2(57568490411.0f));
        float n0, n1, d0, d1;
        unpack2(num, n0, n1); unpack2(den, d0, d1);
        r0 = __fdividef(n0, d0);
        r1 = __fdividef(n1, d1);
    } else if (x0 > 8.0f) {
        float z0 = __fdividef(8.0f, x0), z1 = __fdividef(8.0f, x1);
        ull z = pack2(z0, z1);
        ull y2 = fmul2(z, z);
        ull p1 = C2(0.2093887211e-6f);
        p1 = ffma2(p1, y2, C2(-0.2073370639e-5f));
        p1 = ffma2(p1, y2, C2(0.2734510407e-4f));
        p1 = ffma2(p1, y2, C2(-0.1098628627e-2f));
        p1 = ffma2(p1, y2, C2(1.0f));
        ull p2 = C2(-0.934935152e-7f);
        p2 = ffma2(p2, y2, C2(0.7621095161e-6f));
        p2 = ffma2(p2, y2, C2(-0.6911147651e-5f));
        p2 = ffma2(p2, y2, C2(0.1430488765e-3f));
        p2 = ffma2(p2, y2, C2(-0.1562499995e-1f));
        float p1a, p1b, p2a, p2b;
        unpack2(p1, p1a, p1b); unpack2(p2, p2a, p2b);
        float s0, c0, s1, c1;
        rsincos(x0 - 0.785398164f, &s0, &c0);
        rsincos(x1 - 0.785398164f, &s1, &c1);
        r0 = rsqrtf(x0) * 0.7978845608028654f * (c0 * p1a - z0 * s0 * p2a);
        r1 = rsqrtf(x1) * 0.7978845608028654f * (c1 * p1b - z1 * s1 * p2b);
    } else {
        r0 = bessel_j0f(x0);
        r1 = bessel_j0f(x1);
    }
}

__global__ __launch_bounds__(256, 5)
void bw_psf_kernel(const float* __restrict__ params, float* __restrict__ out) {
    const int p = blockIdx.x;
    const int tid = threadIdx.x;
    const int lane = tid & 31;

    __shared__ __align__(16) float  sA[NI][NRP];   // 14.5 KB
    __shared__ __align__(16) float4 sCS4[7][NI];   // 11.3 KB: (c_z0,s_z0,c_z1,s_z1)
    __shared__ float  sPlane[NHALF + 1][NRP];      // 2.0 KB (row 13 = scratch)
    __shared__ float2 sPair[NHALF][40];            // 4.2 KB
    __shared__ float  sPartF[3][63][17];           // 12.9 KB
    __shared__ float  sWcol[40];

    const float lam = fabsf(params[2 * p]);
    const float n   = fabsf(params[2 * p + 1]);
    const float k   = 6.2831853071795864769f / lam;
    const float kn  = k * n;
    const float kz2 = 0.5f * k * n * n;

    // ---- Phase 1: A[i][r], r-fastest mapping (conflict-free STS) ----
    for (int job = tid; job < 51 * NR; job += 256) {
        int ii = job / NR;
        int r  = job - ii * NR;
        int i0 = 2 * ii;
        int i1 = (i0 < NI - 1) ? i0 + 1 : NI - 1;
        float a = kn * (0.5f * (float)r);
        float rho0 = (float)i0 * 0.01f, rho1 = (float)i1 * 0.01f;
        float j0a, j0b;
        j0_pair(a * rho0, a * rho1, j0a, j0b);
        float tw0 = (i0 == 0 || i0 == NI - 1) ? 0.005f : 0.01f;
        float tw1 = (i1 == NI - 1) ? 0.005f : 0.01f;
        sA[i0][r] = j0a * rho0 * tw0;
        if (i1 != i0) sA[i1][r] = j0b * rho1 * tw1;
    }
    // ---- Phase 2: CS table via z-rotor, threads 128..228 (warps 4-7) ----
    // sign of sin irrelevant (squared later); z chain 0..13 covers zp pairs.
    if (tid >= 128 && tid < 128 + NI) {
        int i = tid - 128;
        float rho = (float)i * 0.01f;
        float th = kz2 * rho * rho;
        float c1, s1;
        rsincos(th, &s1, &c1);
        float c = 1.0f, s = 0.0f;                   // z = 0
        #pragma unroll
        for (int zp = 0; zp < 7; ++zp) {
            float cn = fmaf(c, c1, -(s * s1));      // z = 2zp+1
            float sn = fmaf(s, c1,  (c * s1));
            sCS4[zp][i] = make_float4(c, s, cn, sn);
            c = fmaf(cn, c1, -(sn * s1));           // z = 2zp+2
            s = fmaf(sn, c1,  (cn * s1));
        }
    }
    __syncthreads();

    // ---- Phase 3: z-pair tiled matmul, 252 threads (7 zp x 9 rq x 4 i-groups) ----
    const int g   = tid >> 6;        // i-group 0..3
    const int t64 = tid & 63;
    const bool act = (t64 < 63);
    int zp = 0, r0 = 0;
    ull re01a = 0, re23a = 0, im01a = 0, im23a = 0;
    ull re01b = 0, re23b = 0, im01b = 0, im23b = 0;
    if (act) {
        zp = t64 / 9;
        r0 = (t64 - zp * 9) * 4;
        const int ib = (g == 0) ? 0 : (g * 25 + 1);   // 0, 26, 51, 76
        const int ie = (g + 1) * 25 + 1;              // 26, 51, 76, 101
        #pragma unroll 2
        for (int i = ib; i < ie; ++i) {
            float4 av = *(const float4*)&sA[i][r0];
            float4 cs = sCS4[zp][i];
            ull a01 = pack2(av.x, av.y), a23 = pack2(av.z, av.w);
            ull cc0 = C2(cs.x), ss0 = C2(cs.y);
            ull cc1 = C2(cs.z), ss1 = C2(cs.w);
            re01a = ffma2(a01, cc0, re01a);
            re23a = ffma2(a23, cc0, re23a);
            im01a = ffma2(a01, ss0, im01a);
            im23a = ffma2(a23, ss0, im23a);
            re01b = ffma2(a01, cc1, re01b);
            re23b = ffma2(a23, cc1, re23b);
            im01b = ffma2(a01, ss1, im01b);
            im23b = ffma2(a23, ss1, im23b);
        }
        if (g > 0) {
            float* d = sPartF[g - 1][t64];
            float v0, v1;
            unpack2(re01a, v0, v1); d[0]  = v0; d[1]  = v1;
            unpack2(re23a, v0, v1); d[2]  = v0; d[3]  = v1;
            unpack2(im01a, v0, v1); d[4]  = v0; d[5]  = v1;
            unpack2(im23a, v0, v1); d[6]  = v0; d[7]  = v1;
            unpack2(re01b, v0, v1); d[8]  = v0; d[9]  = v1;
            unpack2(re23b, v0, v1); d[10] = v0; d[11] = v1;
            unpack2(im01b, v0, v1); d[12] = v0; d[13] = v1;
            unpack2(im23b, v0, v1); d[14] = v0; d[15] = v1;
        }
    }
    __syncthreads();
    if (act && g == 0) {
        float vacc[16];
        unpack2(re01a, vacc[0], vacc[1]);   unpack2(re23a, vacc[2],  vacc[3]);
        unpack2(im01a, vacc[4], vacc[5]);   unpack2(im23a, vacc[6],  vacc[7]);
        unpack2(re01b, vacc[8], vacc[9]);   unpack2(re23b, vacc[10], vacc[11]);
        unpack2(im01b, vacc[12], vacc[13]); unpack2(im23b, vacc[14], vacc[15]);
        #pragma unroll
        for (int gg = 0; gg < 3; ++gg) {
            const float* d = sPartF[gg][t64];
            #pragma unroll
            for (int j = 0; j < 16; ++j) vacc[j] += d[j];
        }
        const int z0 = 2 * zp, z1 = z0 + 1;
        sPlane[z0][r0]     = vacc[0] * vacc[0] + vacc[4] * vacc[4];
        sPlane[z0][r0 + 1] = vacc[1] * vacc[1] + vacc[5] * vacc[5];
        sPlane[z0][r0 + 2] = vacc[2] * vacc[2] + vacc[6] * vacc[6];
        sPlane[z1][r0]     = vacc[8] * vacc[8] + vacc[12] * vacc[12];
        sPlane[z1][r0 + 1] = vacc[9] * vacc[9] + vacc[13] * vacc[13];
        sPlane[z1][r0 + 2] = vacc[10] * vacc[10] + vacc[14] * vacc[14];
        if (r0 + 3 < NR) {
            sPlane[z0][r0 + 3] = vacc[3] * vacc[3] + vacc[7] * vacc[7];
            sPlane[z1][r0 + 3] = vacc[11] * vacc[11] + vacc[15] * vacc[15];
        }
    }
    __syncthreads();

    // ---- Phase 4: colsum dot W (norm prep) + pair table ----
    if (tid < NR) {
        float s = sPlane[0][tid];
        #pragma unroll
        for (int zz = 1; zz < NHALF; ++zz) s += 2.0f * sPlane[zz][tid];
        sWcol[tid] = s * g_tabs.W[tid];
    }
    for (int idx = tid; idx < NHALF * NR; idx += 256) {
        int zz = idx / NR, r = idx - zz * NR;
        float lo = sPlane[zz][r];
        float hi = (r < NR - 1) ? sPlane[zz][r + 1] : 0.0f;
        sPair[zz][r] = make_float2(lo, hi);
    }
    __syncthreads();

    // ---- redundant per-warp reduction of sWcol -> inv (no extra barrier) ----
    float v = (lane < NR) ? sWcol[lane] : 0.0f;
    if (lane < 3) v += sWcol[32 + lane];
    #pragma unroll
    for (int o = 16; o; o >>= 1) v += __shfl_xor_sync(0xFFFFFFFFu, v, o);
    const float inv = __fdividef(1.0f, v);

    // ---- Phase 6: interp from constexpr pixel table + z-mirror + write ----
    const float4* ptab = reinterpret_cast<const float4*>(g_tabs.pix);
    for (int pix = tid; pix < 625; pix += 256) {
        float4 e = ptab[pix];                 // {d1, d2, i1 bits, pad}
        int i1 = __float_as_int(e.z);
        float d1 = e.x * inv, d2 = e.y * inv;
        float vv[NHALF];
        #pragma unroll
        for (int zo = 0; zo < NHALF; ++zo) {
            float2 pr = sPair[zo][i1];        // LDS.64
            vv[zo] = fmaf(d1, pr.y, d2 * pr.x);
        }
        float* po = out + (size_t)p * 15625 + pix;
        #pragma unroll
        for (int zz = 0; zz < 25; ++zz) {
            int zo = (zz < 12) ? (12 - zz) : (zz - 12);
            po[zz * 625] = vv[zo];
        }
    }
}

extern "C" void kernel_launch(void* const* d_in, const int* in_sizes, int n_in,
                              void* d_out, int out_size) {
    const float* params = (const float*)d_in[0];
    float* out = (float*)d_out;
    int npairs = in_sizes[0] / 2;   // 16*64 = 1024
    bw_psf_kernel<<<npairs, 256>>>(params, out);
}

// round 12
// speedup vs baseline: 1.2170x; 1.0011x over previous
#include <cuda_runtime.h>
#include <math.h>

// Born-Wolf PSF: params (16,64,2) -> psf (16,64,25,25,25), normalized.
// Fused single kernel, one (b,c) pair per block.
//   phase1: A[i][r] = J0(kn*(r/2)*rho_i)*rho_i*tw_i  (2D mapping, hoisted,
//           conflict-free STS, f32x2-packed J0)
//   phase2: packed CS table sCS4[zp][i] = (cos,sin) for z=2zp,2zp+1 (warps 4-7)
//   phase3: plane[z][r] via z-pair tiled matmul; i=0 dropped (A[0][*]==0),
//           4 uniform fully-unrolled 25-iter groups; 2x LDS.128 + 8 ffma2/iter
//   phase4: colsum dot constexpr W[] -> norm
//   phase6: radial bilinear interp from constexpr pixel table + z-mirror + write

#define NHALF 13
#define NR    35
#define NRP   36
#define NI    101

typedef unsigned long long ull;

// ---------------- compile-time geometry tables ----------------
constexpr double csqrt_(double x) {
    double g = x > 1.0 ? x : 1.0;
    for (int i = 0; i < 64; ++i) g = 0.5 * (g + x / g);
    return g;
}
struct alignas(16) PixEntry { float d1, d2; int i1, pad; };
struct Tabs {
    PixEntry pix[625];
    float W[40];
    constexpr Tabs() : pix(), W() {
        double Wd[40] = {};
        for (int yy = 0; yy < 25; ++yy)
            for (int xx = 0; xx < 25; ++xx) {
                double dx = xx - 12, dy = yy - 12;
                double rp = csqrt_(dx * dx + dy * dy);
                double t2 = 2.0 * rp;
                int i1 = (int)t2;
                double d1 = t2 - (double)i1;
                int q = yy * 25 + xx;
                pix[q].d1 = (float)d1;
                pix[q].d2 = (float)(1.0 - d1);
                pix[q].i1 = i1;
                pix[q].pad = 0;
                Wd[i1]     += 1.0 - d1;
                Wd[i1 + 1] += d1;
            }
        for (int i = 0; i < 40; ++i) W[i] = (float)Wd[i];
    }
};
__device__ constexpr Tabs g_tabs{};

// ---------------- f32x2 packed helpers (sm_100+) ----------------
__device__ __forceinline__ ull pack2(float lo, float hi) {
    ull r; asm("mov.b64 %0, {%1,%2};" : "=l"(r) : "f"(lo), "f"(hi)); return r;
}
__device__ __forceinline__ void unpack2(ull v, float& lo, float& hi) {
    asm("mov.b64 {%0,%1}, %2;" : "=f"(lo), "=f"(hi) : "l"(v));
}
__device__ __forceinline__ ull ffma2(ull a, ull b, ull c) {
    ull d; asm("fma.rn.f32x2 %0, %1, %2, %3;" : "=l"(d) : "l"(a), "l"(b), "l"(c)); return d;
}
__device__ __forceinline__ ull fmul2(ull a, ull b) {
    ull d; asm("mul.rn.f32x2 %0, %1, %2;" : "=l"(d) : "l"(a), "l"(b)); return d;
}
__device__ __forceinline__ ull fadd2(ull a, ull b) {
    ull d; asm("add.rn.f32x2 %0, %1, %2;" : "=l"(d) : "l"(a), "l"(b)); return d;
}
#define C2(c) pack2((c), (c))

// Accurate sincos for |x| up to ~1000: Cody-Waite 2-pi reduction + __sincosf.
__device__ __forceinline__ void rsincos(float x, float* s, float* c) {
    float q = rintf(x * 0.15915494309189535f);
    float r = fmaf(q, -6.28125f, x);
    r = fmaf(q, -1.9353071795864769e-3f, r);
    __sincosf(r, s, c);
}

// Scalar J0 (A&S rational approx, matches reference), fast divides.
__device__ __forceinline__ float bessel_j0f(float x) {
    float ax = fabsf(x);
    if (ax <= 8.0f) {
        float y = x * x;
        float num = -184.9052456f;
        num = fmaf(num, y, 77392.33017f);
        num = fmaf(num, y, -11214424.18f);
        num = fmaf(num, y, 651619640.7f);
        num = fmaf(num, y, -13362590354.0f);
        num = fmaf(num, y, 57568490574.0f);
        float den = y + 267.8532712f;
        den = fmaf(den, y, 59272.64853f);
        den = fmaf(den, y, 9494680.718f);
        den = fmaf(den, y, 1029532985.0f);
        den = fmaf(den, y, 57568490411.0f);
        return __fdividef(num, den);
    } else {
        float z = __fdividef(8.0f, ax);
        float y2 = z * z;
        float p1 = 0.2093887211e-6f;
        p1 = fmaf(p1, y2, -0.2073370639e-5f);
        p1 = fmaf(p1, y2, 0.2734510407e-4f);
        p1 = fmaf(p1, y2, -0.1098628627e-2f);
        p1 = fmaf(p1, y2, 1.0f);
        float p2 = -0.934935152e-7f;
        p2 = fmaf(p2, y2, 0.7621095161e-6f);
        p2 = fmaf(p2, y2, -0.6911147651e-5f);
        p2 = fmaf(p2, y2, 0.1430488765e-3f);
        p2 = fmaf(p2, y2, -0.1562499995e-1f);
        float s, c;
        rsincos(ax - 0.785398164f, &s, &c);
        return rsqrtf(ax) * 0.7978845608028654f * (c * p1 - z * s * p2);
    }
}

// Packed J0 for a pair of non-negative args (x0 <= x1).
__device__ __forceinline__ void j0_pair(float x0, float x1, float& r0, float& r1) {
    if (x1 <= 8.0f) {
        ull x = pack2(x0, x1);
        ull y = fmul2(x, x);
        ull num = C2(-184.9052456f);
        num = ffma2(num, y, C2(77392.33017f));
        num = ffma2(num, y, C2(-11214424.18f));
        num = ffma2(num, y, C2(651619640.7f));
        num = ffma2(num, y, C2(-13362590354.0f));
        num = ffma2(num, y, C2(57568490574.0f));
        ull den = fadd2(y, C2(267.8532712f));
        den = ffma2(den, y, C2(59272.64853f));
        den = ffma2(den, y, C2(9494680.718f));
        den = ffma2(den, y, C2(1029532985.0f));
        den = ffma2(den, y, C2(57568490411.0f));
        float n0, n1, d0, d1;
        unpack2(num, n0, n1); unpack2(den, d0, d1);
        r0 = __fdividef(n0, d0);
        r1 = __fdividef(n1, d1);
    } else if (x0 > 8.0f) {
        float z0 = __fdividef(8.0f, x0), z1 = __fdividef(8.0f, x1);
        ull z = pack2(z0, z1);
        ull y2 = fmul2(z, z);
        ull p1 = C2(0.2093887211e-6f);
        p1 = ffma2(p1, y2, C2(-0.2073370639e-5f));
        p1 = ffma2(p1, y2, C2(0.2734510407e-4f));
        p1 = ffma2(p1, y2, C2(-0.1098628627e-2f));
        p1 = ffma2(p1, y2, C2(1.0f));
        ull p2 = C2(-0.934935152e-7f);
        p2 = ffma2(p2, y2, C2(0.7621095161e-6f));
        p2 = ffma2(p2, y2, C2(-0.6911147651e-5f));
        p2 = ffma2(p2, y2, C2(0.1430488765e-3f));
        p2 = ffma2(p2, y2, C2(-0.1562499995e-1f));
        float p1a, p1b, p2a, p2b;
        unpack2(p1, p1a, p1b); unpack2(p2, p2a, p2b);
        float s0, c0, s1, c1;
        rsincos(x0 - 0.785398164f, &s0, &c0);
        rsincos(x1 - 0.785398164f, &s1, &c1);
        r0 = rsqrtf(x0) * 0.7978845608028654f * (c0 * p1a - z0 * s0 * p2a);
        r1 = rsqrtf(x1) * 0.7978845608028654f * (c1 * p1b - z1 * s1 * p2b);
    } else {
        r0 = bessel_j0f(x0);
        r1 = bessel_j0f(x1);
    }
}

__global__ __launch_bounds__(256, 5)
void bw_psf_kernel(const float* __restrict__ params, float* __restrict__ out) {
    const int p = blockIdx.x;
    const int tid = threadIdx.x;
    const int lane = tid & 31;

    __shared__ __align__(16) float  sA[NI][NRP];   // 14.5 KB
    __shared__ __align__(16) float4 sCS4[7][NI];   // 11.3 KB: (c_z0,s_z0,c_z1,s_z1)
    __shared__ float  sPlane[NHALF + 1][NRP];      // 2.0 KB
    __shared__ float2 sPair[NHALF][40];            // 4.2 KB
    __shared__ float  sPartF[3][63][17];           // 12.9 KB
    __shared__ float  sWcol[40];

    const float lam = fabsf(params[2 * p]);
    const float n   = fabsf(params[2 * p + 1]);
    const float k   = 6.2831853071795864769f / lam;
    const float kn  = k * n;
    const float kz2 = 0.5f * k * n * n;

    // ---- Phase 1: A[i][r], 2D mapping (iit x rr), hoisted, conflict-free ----
    {
        const int rr  = tid & 7;
        const int iit = tid >> 3;
        for (int ii = iit; ii < 51; ii += 32) {
            int i0 = 2 * ii;
            int i1 = (i0 < NI - 1) ? i0 + 1 : NI - 1;
            float rho0 = (float)i0 * 0.01f, rho1 = (float)i1 * 0.01f;
            float b0 = kn * 0.5f * rho0;
            float b1 = kn * 0.5f * rho1;
            float tw0 = (i0 == 0 || i0 == NI - 1) ? 0.005f : 0.01f;
            float m0 = rho0 * tw0;
            float m1 = rho1 * 0.01f;      // i1 is always interior when stored
            for (int r = rr; r < NR; r += 8) {
                float fr = (float)r;
                float j0a, j0b;
                j0_pair(b0 * fr, b1 * fr, j0a, j0b);
                sA[i0][r] = j0a * m0;
                if (i1 != i0) sA[i1][r] = j0b * m1;
            }
        }
    }
    // ---- Phase 2: CS table via z-rotor, threads 128..228 (warps 4-7) ----
    if (tid >= 128 && tid < 128 + NI) {
        int i = tid - 128;
        float rho = (float)i * 0.01f;
        float th = kz2 * rho * rho;
        float c1, s1;
        rsincos(th, &s1, &c1);
        float c = 1.0f, s = 0.0f;                   // z = 0
        #pragma unroll
        for (int zp = 0; zp < 7; ++zp) {
            float cn = fmaf(c, c1, -(s * s1));      // z = 2zp+1
            float sn = fmaf(s, c1,  (c * s1));
            sCS4[zp][i] = make_float4(c, s, cn, sn);
            c = fmaf(cn, c1, -(sn * s1));           // z = 2zp+2
            s = fmaf(sn, c1,  (cn * s1));
        }
    }
    __syncthreads();

    // ---- Phase 3: z-pair tiled matmul; i=0 dropped (A[0][*] == 0 exactly) ----
    // 252 threads: 7 zp x 9 rq x 4 i-groups, each a uniform 25-iter unrolled loop.
    const int g   = tid >> 6;        // i-group 0..3
    const int t64 = tid & 63;
    const bool act = (t64 < 63);
    int zp = 0, r0 = 0;
    ull re01a = 0, re23a = 0, im01a = 0, im23a = 0;
    ull re01b = 0, re23b = 0, im01b = 0, im23b = 0;
    if (act) {
        zp = t64 / 9;
        r0 = (t64 - zp * 9) * 4;
        const int ib = g * 25 + 1;    // 1, 26, 51, 76 (i=0 contributes zero)
        #pragma unroll
        for (int t = 0; t < 25; ++t) {
            const int i = ib + t;
            float4 av = *(const float4*)&sA[i][r0];
            float4 cs = sCS4[zp][i];
            ull a01 = pack2(av.x, av.y), a23 = pack2(av.z, av.w);
            ull cc0 = C2(cs.x), ss0 = C2(cs.y);
            ull cc1 = C2(cs.z), ss1 = C2(cs.w);
            re01a = ffma2(a01, cc0, re01a);
            re23a = ffma2(a23, cc0, re23a);
            im01a = ffma2(a01, ss0, im01a);
            im23a = ffma2(a23, ss0, im23a);
            re01b = ffma2(a01, cc1, re01b);
            re23b = ffma2(a23, cc1, re23b);
            im01b = ffma2(a01, ss1, im01b);
            im23b = ffma2(a23, ss1, im23b);
        }
        if (g > 0) {
            float* d = sPartF[g - 1][t64];
            float v0, v1;
            unpack2(re01a, v0, v1); d[0]  = v0; d[1]  = v1;
            unpack2(re23a, v0, v1); d[2]  = v0; d[3]  = v1;
            unpack2(im01a, v0, v1); d[4]  = v0; d[5]  = v1;
            unpack2(im23a, v0, v1); d[6]  = v0; d[7]  = v1;
            unpack2(re01b, v0, v1); d[8]  = v0; d[9]  = v1;
            unpack2(re23b, v0, v1); d[10] = v0; d[11] = v1;
            unpack2(im01b, v0, v1); d[12] = v0; d[13] = v1;
            unpack2(im23b, v0, v1); d[14] = v0; d[15] = v1;
        }
    }
    __syncthreads();
    if (act && g == 0) {
        float vacc[16];
        unpack2(re01a, vacc[0], vacc[1]);   unpack2(re23a, vacc[2],  vacc[3]);
        unpack2(im01a, vacc[4], vacc[5]);   unpack2(im23a, vacc[6],  vacc[7]);
        unpack2(re01b, vacc[8], vacc[9]);   unpack2(re23b, vacc[10], vacc[11]);
        unpack2(im01b, vacc[12], vacc[13]); unpack2(im23b, vacc[14], vacc[15]);
        #pragma unroll
        for (int gg = 0; gg < 3; ++gg) {
            const float* d = sPartF[gg][t64];
            #pragma unroll
            for (int j = 0; j < 16; ++j) vacc[j] += d[j];
        }
        const int z0 = 2 * zp, z1 = z0 + 1;
        sPlane[z0][r0]     = vacc[0] * vacc[0] + vacc[4] * vacc[4];
        sPlane[z0][r0 + 1] = vacc[1] * vacc[1] + vacc[5] * vacc[5];
        sPlane[z0][r0 + 2] = vacc[2] * vacc[2] + vacc[6] * vacc[6];
        sPlane[z1][r0]     = vacc[8] * vacc[8] + vacc[12] * vacc[12];
        sPlane[z1][r0 + 1] = vacc[9] * vacc[9] + vacc[13] * vacc[13];
        sPlane[z1][r0 + 2] = vacc[10] * vacc[10] + vacc[14] * vacc[14];
        if (r0 + 3 < NR) {
            sPlane[z0][r0 + 3] = vacc[3] * vacc[3] + vacc[7] * vacc[7];
            sPlane[z1][r0 + 3] = vacc[11] * vacc[11] + vacc[15] * vacc[15];
        }
    }
    __syncthreads();

    // ---- Phase 4: colsum dot W (norm prep) + pair table ----
    if (tid < NR) {
        float s = sPlane[0][tid];
        #pragma unroll
        for (int zz = 1; zz < NHALF; ++zz) s += 2.0f * sPlane[zz][tid];
        sWcol[tid] = s * g_tabs.W[tid];
    }
    for (int idx = tid; idx < NHALF * NR; idx += 256) {
        int zz = idx / NR, r = idx - zz * NR;
        float lo = sPlane[zz][r];
        float hi = (r < NR - 1) ? sPlane[zz][r + 1] : 0.0f;
        sPair[zz][r] = make_float2(lo, hi);
    }
    __syncthreads();

    // ---- redundant per-warp reduction of sWcol -> inv (no extra barrier) ----
    float v = (lane < NR) ? sWcol[lane] : 0.0f;
    if (lane < 3) v += sWcol[32 + lane];
    #pragma unroll
    for (int o = 16; o; o >>= 1) v += __shfl_xor_sync(0xFFFFFFFFu, v, o);
    const float inv = __fdividef(1.0f, v);

    // ---- Phase 6: interp from constexpr pixel table + z-mirror + write ----
    const float4* ptab = reinterpret_cast<const float4*>(g_tabs.pix);
    #pragma unroll
    for (int rep = 0; rep < 3; ++rep) {
        int pix = tid + rep * 256;
        if (pix < 625) {
            float4 e = ptab[pix];                 // {d1, d2, i1 bits, pad}
            int i1 = __float_as_int(e.z);
            float d1 = e.x * inv, d2 = e.y * inv;
            float vv[NHALF];
            #pragma unroll
            for (int zo = 0; zo < NHALF; ++zo) {
                float2 pr = sPair[zo][i1];        // LDS.64
                vv[zo] = fmaf(d1, pr.y, d2 * pr.x);
            }
            float* po = out + (size_t)p * 15625 + pix;
            #pragma unroll
            for (int zz = 0; zz < 25; ++zz) {
                int zo = (zz < 12) ? (12 - zz) : (zz - 12);
                po[zz * 625] = vv[zo];
            }
        }
    }
}

extern "C" void kernel_launch(void* const* d_in, const int* in_sizes, int n_in,
                              void* d_out, int out_size) {
    const float* params = (const float*)d_in[0];
    float* out = (float*)d_out;
    int npairs = in_sizes[0] / 2;   // 16*64 = 1024
    bw_psf_kernel<<<npairs, 256>>>(params, out);
}